// round 5
// baseline (speedup 1.0000x reference)
#include <cuda_runtime.h>
#include <cstdint>
#include <math.h>

#define V_NUM   100000
#define R_NUM   100000
#define EMBD    128
#define NBRS    20
#define NCLS    10
#define DT_ROWS 200004
#define DT_OFF  100000

// ---------------- scratch tables (device globals; no allocation allowed) ----
__device__ float g_tabQ  [(size_t)V_NUM * 128];   //  51.2 MB : Wq_v@v_emb + (Wq_t@cos(tb)+bq)
__device__ float g_tabKVv[(size_t)V_NUM * 256];   // 102.4 MB : [Wk_v@v_emb | Wv_v@v_emb]
__device__ float g_tabKVr[(size_t)R_NUM * 256];   // 102.4 MB : [Wk_r@r_emb | Wv_r@r_emb]
__device__ float g_tabKVt[(size_t)DT_ROWS * 256]; // 204.8 MB : [Wk_t@e+bk | Wv_t@e+bv] per dt
__device__ float g_qcb [128];
__device__ float g_Wco [NCLS * 128];              // Wc @ Wo
__device__ float g_bco [NCLS];                    // Wc @ bo + bc
__device__ float g_WtT [128 * 256];               // time-weight slices, [c][o] layout
__device__ int   g_is64;                          // node_data dtype flag (1 = int64)
__device__ int   g_mask32;                        // nbr_mask dtype flag (1 = int32, 0 = uint8)

// Accurate cosine regardless of fast-math: exact fp32 phase (matches reference),
// double-precision range reduction to [-pi, pi], then cosf (accurate there).
__device__ __forceinline__ float cos_acc(float x)
{
    float k = rintf(x * 0.15915494309189535f);        // x / (2*pi)
    double r = (double)x - (double)k * 6.283185307179586476925286766559;
    return cosf((float)r);
}

// ---------------- dtype detects ----------------------------------------------
// node_data: int64 layout has every odd 32-bit word == 0.
__global__ void tgn_detect_node(const int* __restrict__ node, int n_words)
{
    __shared__ int sOr[256];
    int t = threadIdx.x;
    int acc = 0;
    for (int i = 1 + 2 * t; i < n_words; i += 512) acc |= node[i];
    sOr[t] = acc;
    __syncthreads();
    for (int s = 128; s; s >>= 1) { if (t < s) sOr[t] |= sOr[t + s]; __syncthreads(); }
    if (t == 0) g_is64 = (sOr[0] == 0) ? 1 : 0;
}

// nbr_mask: int32 {0,1} layout has every byte at pos%4!=0 == 0 within the first
// n_elems bytes (safe to read for both layouts). uint8 bool has random 1s there.
__global__ void tgn_detect_mask(const unsigned char* __restrict__ m, int n_elems)
{
    __shared__ int sOr[256];
    int t = threadIdx.x;
    int acc = 0;
    for (int i = t; i < n_elems; i += 256)
        if (i & 3) acc |= m[i];
    sOr[t] = acc;
    __syncthreads();
    for (int s = 128; s; s >>= 1) { if (t < s) sOr[t] |= sOr[t + s]; __syncthreads(); }
    if (t == 0) g_mask32 = (sOr[0] == 0) ? 1 : 0;
}

// ---------------- prep: small constants --------------------------------------
__global__ void tgn_prep(const float* __restrict__ Wq, const float* __restrict__ bq,
                         const float* __restrict__ Wk, const float* __restrict__ Wv,
                         const float* __restrict__ Wo, const float* __restrict__ bo,
                         const float* __restrict__ Wc, const float* __restrict__ bc,
                         const float* __restrict__ tb)
{
    int t = threadIdx.x;  // 128 threads
    float acc = bq[t];
    for (int c = 0; c < 128; ++c) acc += Wq[t * 256 + 128 + c] * cos_acc(tb[c]);
    g_qcb[t] = acc;
    for (int o = 0; o < 256; ++o) {
        float w = (o < 128) ? Wk[o * 384 + 256 + t] : Wv[(o - 128) * 384 + 256 + t];
        g_WtT[t * 256 + o] = w;
    }
    for (int c = 0; c < NCLS; ++c) {
        float s = 0.f;
        for (int m = 0; m < 128; ++m) s += Wc[c * 128 + m] * Wo[m * 128 + t];
        g_Wco[c * 128 + t] = s;
    }
    if (t < NCLS) {
        float s = bc[t];
        for (int m = 0; m < 128; ++m) s += Wc[t * 128 + m] * bo[m];
        g_bco[t] = s;
    }
}

// ---------------- table GEMMs: C[M x 64cols] = A[M x 128] @ W_slice^T --------
struct Slice  { const float* W; int ldw; int tab; int ldc; int cofs; int useAdd; };
struct Slice6 { Slice s[6]; };

__global__ void tgn_gemm(const float* __restrict__ A, int M, Slice6 P)
{
    __shared__ float As[16][68];
    __shared__ float Bs[16][68];
    Slice sl = P.s[blockIdx.y];
    float* C = (sl.tab == 0) ? g_tabQ : (sl.tab == 1) ? g_tabKVv : g_tabKVr;

    int m0  = blockIdx.x * 64;
    int tid = threadIdx.x;            // 256 threads
    int lm  = tid >> 2;               // 0..63
    int lk  = (tid & 3) << 2;         // 0,4,8,12
    int ty  = tid >> 4;               // 0..15 (m group)
    int tx  = tid & 15;               // 0..15 (n group)

    float acc[4][4] = {};
    for (int kk = 0; kk < 128; kk += 16) {
        int row = m0 + lm;
        float4 av = make_float4(0.f, 0.f, 0.f, 0.f);
        if (row < M) av = *reinterpret_cast<const float4*>(&A[(size_t)row * 128 + kk + lk]);
        float4 bv = *reinterpret_cast<const float4*>(&sl.W[(size_t)lm * sl.ldw + kk + lk]);
        __syncthreads();
        As[lk + 0][lm] = av.x; As[lk + 1][lm] = av.y; As[lk + 2][lm] = av.z; As[lk + 3][lm] = av.w;
        Bs[lk + 0][lm] = bv.x; Bs[lk + 1][lm] = bv.y; Bs[lk + 2][lm] = bv.z; Bs[lk + 3][lm] = bv.w;
        __syncthreads();
#pragma unroll
        for (int k = 0; k < 16; ++k) {
            float4 a4 = *reinterpret_cast<float4*>(&As[k][ty << 2]);
            float4 b4 = *reinterpret_cast<float4*>(&Bs[k][tx << 2]);
            acc[0][0] += a4.x * b4.x; acc[0][1] += a4.x * b4.y; acc[0][2] += a4.x * b4.z; acc[0][3] += a4.x * b4.w;
            acc[1][0] += a4.y * b4.x; acc[1][1] += a4.y * b4.y; acc[1][2] += a4.y * b4.z; acc[1][3] += a4.y * b4.w;
            acc[2][0] += a4.z * b4.x; acc[2][1] += a4.z * b4.y; acc[2][2] += a4.z * b4.z; acc[2][3] += a4.z * b4.w;
            acc[3][0] += a4.w * b4.x; acc[3][1] += a4.w * b4.y; acc[3][2] += a4.w * b4.z; acc[3][3] += a4.w * b4.w;
        }
    }
    float add0 = 0.f, add1 = 0.f, add2 = 0.f, add3 = 0.f;
    if (sl.useAdd) {
        add0 = g_qcb[sl.cofs + (tx << 2) + 0];
        add1 = g_qcb[sl.cofs + (tx << 2) + 1];
        add2 = g_qcb[sl.cofs + (tx << 2) + 2];
        add3 = g_qcb[sl.cofs + (tx << 2) + 3];
    }
#pragma unroll
    for (int i = 0; i < 4; ++i) {
        int row = m0 + (ty << 2) + i;
        if (row < M) {
            float4 o;
            o.x = acc[i][0] + add0; o.y = acc[i][1] + add1;
            o.z = acc[i][2] + add2; o.w = acc[i][3] + add3;
            *reinterpret_cast<float4*>(&C[(size_t)row * sl.ldc + sl.cofs + (tx << 2)]) = o;
        }
    }
}

// ---------------- dt table: tabKVt[dt] = [Wk_t@cos(dt*w+b)+bk | Wv_t@...+bv] -
__global__ void tgn_dt(const float* __restrict__ bk, const float* __restrict__ bv,
                       const float* __restrict__ tw, const float* __restrict__ tb)
{
    __shared__ float sE[4][128];
    int t = threadIdx.x;              // 256 threads; thread t owns output column t
    float bias = (t < 128) ? bk[t] : bv[t - 128];
    int   c  = t & 127;
    int   d0 = t >> 7;                // 0 or 1
    float wc  = tw[c];
    float bcv = tb[c];

    for (long q0 = (long)blockIdx.x * 4; q0 < DT_ROWS; q0 += (long)gridDim.x * 4) {
        float dv0 = (float)(q0 + d0     - DT_OFF);
        float dv1 = (float)(q0 + d0 + 2 - DT_OFF);
        sE[d0    ][c] = cos_acc(dv0 * wc + bcv);
        sE[d0 + 2][c] = cos_acc(dv1 * wc + bcv);
        __syncthreads();
        float a0 = bias, a1 = bias, a2 = bias, a3 = bias;
#pragma unroll 8
        for (int cc = 0; cc < 128; cc += 4) {
            float4 e0 = *reinterpret_cast<float4*>(&sE[0][cc]);
            float4 e1 = *reinterpret_cast<float4*>(&sE[1][cc]);
            float4 e2 = *reinterpret_cast<float4*>(&sE[2][cc]);
            float4 e3 = *reinterpret_cast<float4*>(&sE[3][cc]);
            float w0 = g_WtT[(cc + 0) * 256 + t];
            float w1 = g_WtT[(cc + 1) * 256 + t];
            float w2 = g_WtT[(cc + 2) * 256 + t];
            float w3 = g_WtT[(cc + 3) * 256 + t];
            a0 += w0 * e0.x; a1 += w0 * e1.x; a2 += w0 * e2.x; a3 += w0 * e3.x;
            a0 += w1 * e0.y; a1 += w1 * e1.y; a2 += w1 * e2.y; a3 += w1 * e3.y;
            a0 += w2 * e0.z; a1 += w2 * e1.z; a2 += w2 * e2.z; a3 += w2 * e3.z;
            a0 += w3 * e0.w; a1 += w3 * e1.w; a2 += w3 * e2.w; a3 += w3 * e3.w;
        }
        float* outp = &g_tabKVt[(size_t)q0 * 256 + t];
        outp[0]   = a0; outp[256] = a1; outp[512] = a2; outp[768] = a3;
        __syncthreads();
    }
}

// ---------------- attention + epilogue: one block (128 thr) per node --------
__global__ void tgn_attn(const int* __restrict__ node, const int* __restrict__ nbr,
                         const void* __restrict__ maskp,
                         const float* __restrict__ bc,
                         float* __restrict__ out, int N)
{
    int i = blockIdx.x;
    if (i >= N) return;
    int tid = threadIdx.x, w = tid >> 5, l = tid & 31;
    __shared__ float sPart[4][128];
    __shared__ int   sUnm[4];

    int v, tq;
    if (g_is64) { v = node[i * 8 + 0]; tq = node[i * 8 + 4]; }
    else        { v = node[i * 4 + 0]; tq = node[i * 4 + 2]; }

    const int*           maski = (const int*)maskp;
    const unsigned char* maskb = (const unsigned char*)maskp;
    int m32 = g_mask32;

    const float* qrow = &g_tabQ[(size_t)v * 128];
    float q0 = qrow[l], q1 = qrow[l + 32], q2 = qrow[l + 64], q3 = qrow[l + 96];

    float o0 = 0.f, o1 = 0.f, o2 = 0.f, o3 = 0.f;
    int unm = 0;

    for (int j = w; j < NBRS; j += 4) {
        int eb = (i * NBRS + j) * 3;
        int nv = nbr[eb], nr = nbr[eb + 1], nt = nbr[eb + 2];
        int m  = m32 ? maski[i * NBRS + j] : (int)maskb[i * NBRS + j];
        int di = tq - nt + DT_OFF;
        di = min(max(di, 0), DT_ROWS - 1);
        const float* pv = &g_tabKVv[(size_t)nv * 256];
        const float* pr = &g_tabKVr[(size_t)nr * 256];
        const float* pt = &g_tabKVt[(size_t)di * 256];
        float k0 = pv[l      ] + pr[l      ] + pt[l      ];
        float k1 = pv[l +  32] + pr[l +  32] + pt[l +  32];
        float k2 = pv[l +  64] + pr[l +  64] + pt[l +  64];
        float k3 = pv[l +  96] + pr[l +  96] + pt[l +  96];
        float v0 = pv[l + 128] + pr[l + 128] + pt[l + 128];
        float v1 = pv[l + 160] + pr[l + 160] + pt[l + 160];
        float v2 = pv[l + 192] + pr[l + 192] + pt[l + 192];
        float v3 = pv[l + 224] + pr[l + 224] + pt[l + 224];

        float p0 = q0 * k0 + q1 * k1;   // head 0 partial (dims l, l+32)
        float p1 = q2 * k2 + q3 * k3;   // head 1 partial (dims l+64, l+96)
#pragma unroll
        for (int off = 16; off; off >>= 1) {
            p0 += __shfl_xor_sync(0xffffffffu, p0, off);
            p1 += __shfl_xor_sync(0xffffffffu, p1, off);
        }
        float a0, a1;
        if (m) { a0 = 0.5f; a1 = 0.5f; }     // masked: both scores -1e9 -> softmax = (.5,.5)
        else {
            const float sc = 0.08838834764831843f;  // 1/sqrt(128)
            float s0 = p0 * sc, s1 = p1 * sc;
            float mx = fmaxf(s0, s1);
            float e0 = expf(s0 - mx), e1 = expf(s1 - mx);
            float inv = 1.0f / (e0 + e1);
            a0 = e0 * inv; a1 = e1 * inv;
            unm++;
        }
        o0 += a0 * v0; o1 += a0 * v1; o2 += a1 * v2; o3 += a1 * v3;
    }

    sPart[w][l] = o0; sPart[w][l + 32] = o1; sPart[w][l + 64] = o2; sPart[w][l + 96] = o3;
    if (l == 0) sUnm[w] = unm;
    __syncthreads();
    int tot = sUnm[0] + sUnm[1] + sUnm[2] + sUnm[3];

    float f0 = sPart[0][l     ] + sPart[1][l     ] + sPart[2][l     ] + sPart[3][l     ];
    float f1 = sPart[0][l + 32] + sPart[1][l + 32] + sPart[2][l + 32] + sPart[3][l + 32];
    float f2 = sPart[0][l + 64] + sPart[1][l + 64] + sPart[2][l + 64] + sPart[3][l + 64];
    float f3 = sPart[0][l + 96] + sPart[1][l + 96] + sPart[2][l + 96] + sPart[3][l + 96];

    for (int c = w; c < NCLS; c += 4) {
        const float* wr = &g_Wco[c * 128];
        float p = wr[l] * f0 + wr[l + 32] * f1 + wr[l + 64] * f2 + wr[l + 96] * f3;
#pragma unroll
        for (int off = 16; off; off >>= 1) p += __shfl_xor_sync(0xffffffffu, p, off);
        if (l == 0) out[(size_t)i * NCLS + c] = (tot == 0) ? bc[c] : (g_bco[c] + p);
    }
}

// ---------------- launch ------------------------------------------------------
extern "C" void kernel_launch(void* const* d_in, const int* in_sizes, int n_in,
                              void* d_out, int out_size)
{
    const int*   node  = (const int*)d_in[0];
    const int*   nbr   = (const int*)d_in[1];
    const void*  mask  = d_in[2];
    const float* v_emb = (const float*)d_in[3];
    const float* r_emb = (const float*)d_in[4];
    const float* tw    = (const float*)d_in[5];
    const float* tb    = (const float*)d_in[6];
    const float* Wq    = (const float*)d_in[7];
    const float* bq    = (const float*)d_in[8];
    const float* Wk    = (const float*)d_in[9];
    const float* bk    = (const float*)d_in[10];
    const float* Wv    = (const float*)d_in[11];
    const float* bv    = (const float*)d_in[12];
    const float* Wo    = (const float*)d_in[13];
    const float* bo    = (const float*)d_in[14];
    const float* Wc    = (const float*)d_in[15];
    const float* bc    = (const float*)d_in[16];
    float* out = (float*)d_out;

    int N  = in_sizes[0] / 4;
    int Mv = in_sizes[3] / 128;
    int Mr = in_sizes[4] / 128;

    tgn_detect_node<<<1, 256>>>(node, in_sizes[0]);
    tgn_detect_mask<<<1, 256>>>((const unsigned char*)mask, in_sizes[2]);

    tgn_prep<<<1, 128>>>(Wq, bq, Wk, Wv, Wo, bo, Wc, bc, tb);

    Slice6 Pv;
    Pv.s[0] = { Wq,                  256, 0, 128,   0, 1 };
    Pv.s[1] = { Wq + 64 * 256,       256, 0, 128,  64, 1 };
    Pv.s[2] = { Wk,                  384, 1, 256,   0, 0 };
    Pv.s[3] = { Wk + 64 * 384,       384, 1, 256,  64, 0 };
    Pv.s[4] = { Wv,                  384, 1, 256, 128, 0 };
    Pv.s[5] = { Wv + 64 * 384,       384, 1, 256, 192, 0 };
    dim3 g1((Mv + 63) / 64, 6);
    tgn_gemm<<<g1, 256>>>(v_emb, Mv, Pv);

    Slice6 Pr;
    Pr.s[0] = { Wk + 128,            384, 2, 256,   0, 0 };
    Pr.s[1] = { Wk + 64 * 384 + 128, 384, 2, 256,  64, 0 };
    Pr.s[2] = { Wv + 128,            384, 2, 256, 128, 0 };
    Pr.s[3] = { Wv + 64 * 384 + 128, 384, 2, 256, 192, 0 };
    Pr.s[4] = Pr.s[0];
    Pr.s[5] = Pr.s[0];
    dim3 g2((Mr + 63) / 64, 4);
    tgn_gemm<<<g2, 256>>>(r_emb, Mr, Pr);

    tgn_dt<<<592, 256>>>(bk, bv, tw, tb);

    tgn_attn<<<N, 128>>>(node, nbr, mask, bc, out, N);
}

// round 7
// speedup vs baseline: 1.2460x; 1.2460x over previous
#include <cuda_runtime.h>
#include <cuda_fp16.h>
#include <cstdint>
#include <math.h>

#define V_NUM   100000
#define R_NUM   100000
#define EMBD    128
#define NBRS    20
#define NCLS    10
#define DT_ROWS 200004
#define DT_OFF  100000

// ---------------- scratch tables (device globals; fp16 to halve gather BW) --
__device__ __half g_tabQ_h  [(size_t)V_NUM * 128];   //  25.6 MB
__device__ __half g_tabKVv_h[(size_t)V_NUM * 256];   //  51.2 MB
__device__ __half g_tabKVr_h[(size_t)R_NUM * 256];   //  51.2 MB
__device__ __half g_tabKVt_h[(size_t)DT_ROWS * 256]; // 102.4 MB
__device__ float g_qcb [128];
__device__ float g_Wco [NCLS * 128];              // Wc @ Wo
__device__ float g_bco [NCLS];                    // Wc @ bo + bc
__device__ float g_WtT [128 * 256];               // time-weight slices, [c][o] layout
__device__ int   g_is64;                          // node_data dtype flag (1 = int64)
__device__ int   g_mask32;                        // nbr_mask dtype flag (1 = int32)

// Accurate cosine regardless of fast-math: exact fp32 phase, DP range reduction.
__device__ __forceinline__ float cos_acc(float x)
{
    float k = rintf(x * 0.15915494309189535f);
    double r = (double)x - (double)k * 6.283185307179586476925286766559;
    return cosf((float)r);
}

__device__ __forceinline__ float2 sum3h(__half2 a, __half2 b, __half2 c)
{
    float2 x = __half22float2(a), y = __half22float2(b), z = __half22float2(c);
    return make_float2(x.x + y.x + z.x, x.y + y.y + z.y);
}

// ---------------- dtype detects ----------------------------------------------
__global__ void tgn_detect_node(const int* __restrict__ node, int n_words)
{
    __shared__ int sOr[256];
    int t = threadIdx.x;
    int acc = 0;
    for (int i = 1 + 2 * t; i < n_words; i += 512) acc |= node[i];
    sOr[t] = acc;
    __syncthreads();
    for (int s = 128; s; s >>= 1) { if (t < s) sOr[t] |= sOr[t + s]; __syncthreads(); }
    if (t == 0) g_is64 = (sOr[0] == 0) ? 1 : 0;
}

__global__ void tgn_detect_mask(const unsigned char* __restrict__ m, int n_elems)
{
    __shared__ int sOr[256];
    int t = threadIdx.x;
    int acc = 0;
    for (int i = t; i < n_elems; i += 256)
        if (i & 3) acc |= m[i];
    sOr[t] = acc;
    __syncthreads();
    for (int s = 128; s; s >>= 1) { if (t < s) sOr[t] |= sOr[t + s]; __syncthreads(); }
    if (t == 0) g_mask32 = (sOr[0] == 0) ? 1 : 0;
}

// ---------------- prep: small constants --------------------------------------
__global__ void tgn_prep(const float* __restrict__ Wq, const float* __restrict__ bq,
                         const float* __restrict__ Wk, const float* __restrict__ Wv,
                         const float* __restrict__ Wo, const float* __restrict__ bo,
                         const float* __restrict__ Wc, const float* __restrict__ bc,
                         const float* __restrict__ tb)
{
    int t = threadIdx.x;  // 128 threads
    float acc = bq[t];
    for (int c = 0; c < 128; ++c) acc += Wq[t * 256 + 128 + c] * cos_acc(tb[c]);
    g_qcb[t] = acc;
    for (int o = 0; o < 256; ++o) {
        float w = (o < 128) ? Wk[o * 384 + 256 + t] : Wv[(o - 128) * 384 + 256 + t];
        g_WtT[t * 256 + o] = w;
    }
    for (int c = 0; c < NCLS; ++c) {
        float s = 0.f;
        for (int m = 0; m < 128; ++m) s += Wc[c * 128 + m] * Wo[m * 128 + t];
        g_Wco[c * 128 + t] = s;
    }
    if (t < NCLS) {
        float s = bc[t];
        for (int m = 0; m < 128; ++m) s += Wc[t * 128 + m] * bo[m];
        g_bco[t] = s;
    }
}

// ---------------- table GEMMs: C[128-tile x 128cols] = A @ W_slice^T, fp16 out
struct Slice  { const float* W; int ldw; int tab; int ldc; int cofs; int useAdd; };
struct Slice3 { Slice s[3]; };

__global__ __launch_bounds__(256, 2)
void tgn_gemm(const float* __restrict__ A, int M, Slice3 P)
{
    __shared__ float As[16][132];
    __shared__ float Bs[16][132];
    Slice sl = P.s[blockIdx.y];
    __half* C = (sl.tab == 0) ? g_tabQ_h : (sl.tab == 1) ? g_tabKVv_h : g_tabKVr_h;

    int m0  = blockIdx.x * 128;
    int tid = threadIdx.x;            // 256 threads
    int lr  = tid >> 1;               // 0..127 (tile row)
    int lk  = (tid & 1) * 8;          // 0 or 8
    int ty  = tid >> 4;               // 0..15 (8-row group)
    int tx  = tid & 15;               // 0..15 (8-col group)

    float acc[8][8] = {};
    for (int kk = 0; kk < 128; kk += 16) {
        int row = m0 + lr;
        float4 a0 = make_float4(0.f,0.f,0.f,0.f), a1 = a0;
        if (row < M) {
            a0 = *reinterpret_cast<const float4*>(&A[(size_t)row * 128 + kk + lk]);
            a1 = *reinterpret_cast<const float4*>(&A[(size_t)row * 128 + kk + lk + 4]);
        }
        float4 b0 = *reinterpret_cast<const float4*>(&sl.W[(size_t)lr * sl.ldw + kk + lk]);
        float4 b1 = *reinterpret_cast<const float4*>(&sl.W[(size_t)lr * sl.ldw + kk + lk + 4]);
        __syncthreads();
        As[lk+0][lr]=a0.x; As[lk+1][lr]=a0.y; As[lk+2][lr]=a0.z; As[lk+3][lr]=a0.w;
        As[lk+4][lr]=a1.x; As[lk+5][lr]=a1.y; As[lk+6][lr]=a1.z; As[lk+7][lr]=a1.w;
        Bs[lk+0][lr]=b0.x; Bs[lk+1][lr]=b0.y; Bs[lk+2][lr]=b0.z; Bs[lk+3][lr]=b0.w;
        Bs[lk+4][lr]=b1.x; Bs[lk+5][lr]=b1.y; Bs[lk+6][lr]=b1.z; Bs[lk+7][lr]=b1.w;
        __syncthreads();
#pragma unroll
        for (int k = 0; k < 16; ++k) {
            float4 aA = *reinterpret_cast<float4*>(&As[k][ty * 8]);
            float4 aB = *reinterpret_cast<float4*>(&As[k][ty * 8 + 4]);
            float4 bA = *reinterpret_cast<float4*>(&Bs[k][tx * 8]);
            float4 bB = *reinterpret_cast<float4*>(&Bs[k][tx * 8 + 4]);
            float av[8] = {aA.x,aA.y,aA.z,aA.w,aB.x,aB.y,aB.z,aB.w};
            float bv[8] = {bA.x,bA.y,bA.z,bA.w,bB.x,bB.y,bB.z,bB.w};
#pragma unroll
            for (int i = 0; i < 8; ++i)
#pragma unroll
                for (int j = 0; j < 8; ++j)
                    acc[i][j] += av[i] * bv[j];
        }
    }
    float add[8];
#pragma unroll
    for (int j = 0; j < 8; ++j)
        add[j] = sl.useAdd ? g_qcb[tx * 8 + j] : 0.f;
#pragma unroll
    for (int i = 0; i < 8; ++i) {
        int row = m0 + ty * 8 + i;
        if (row < M) {
            __align__(16) __half2 h[4];
#pragma unroll
            for (int j = 0; j < 4; ++j)
                h[j] = __floats2half2_rn(acc[i][2*j] + add[2*j], acc[i][2*j+1] + add[2*j+1]);
            *reinterpret_cast<uint4*>(&C[(size_t)row * sl.ldc + sl.cofs + tx * 8]) =
                *reinterpret_cast<uint4*>(h);
        }
    }
}

// ---------------- dt table: 8 rows per block ---------------------------------
__global__ void tgn_dt(const float* __restrict__ bk, const float* __restrict__ bv,
                       const float* __restrict__ tw, const float* __restrict__ tb)
{
    __shared__ float sE[8][128];
    int t = threadIdx.x;              // 256 threads; thread t owns output column t
    float bias = (t < 128) ? bk[t] : bv[t - 128];
    int   c  = t & 127;
    int   d0 = t >> 7;                // 0 or 1
    float wc  = tw[c];
    float bcv = tb[c];

    long q0 = (long)blockIdx.x * 8;
#pragma unroll
    for (int rr = 0; rr < 4; ++rr) {
        int row = d0 + rr * 2;
        float dv = (float)(q0 + row - DT_OFF);
        sE[row][c] = cos_acc(dv * wc + bcv);
    }
    __syncthreads();
    float a[8];
#pragma unroll
    for (int r = 0; r < 8; ++r) a[r] = bias;
#pragma unroll 4
    for (int cc = 0; cc < 128; cc += 4) {
        float4 e[8];
#pragma unroll
        for (int r = 0; r < 8; ++r)
            e[r] = *reinterpret_cast<float4*>(&sE[r][cc]);
        float w0 = g_WtT[(cc + 0) * 256 + t];
        float w1 = g_WtT[(cc + 1) * 256 + t];
        float w2 = g_WtT[(cc + 2) * 256 + t];
        float w3 = g_WtT[(cc + 3) * 256 + t];
#pragma unroll
        for (int r = 0; r < 8; ++r)
            a[r] += w0 * e[r].x + w1 * e[r].y + w2 * e[r].z + w3 * e[r].w;
    }
#pragma unroll
    for (int r = 0; r < 8; ++r)
        if (q0 + r < DT_ROWS)
            g_tabKVt_h[(size_t)(q0 + r) * 256 + t] = __float2half_rn(a[r]);
}

// ---------------- attention + epilogue: one block (128 thr) per node --------
__global__ void tgn_attn(const int* __restrict__ node, const int* __restrict__ nbr,
                         const void* __restrict__ maskp,
                         const float* __restrict__ bc,
                         float* __restrict__ out, int N)
{
    int i = blockIdx.x;
    if (i >= N) return;
    int tid = threadIdx.x, w = tid >> 5, l = tid & 31;
    __shared__ float sPart[4][128];
    __shared__ int   sUnm[4];

    int v, tq;
    if (g_is64) { v = node[i * 8 + 0]; tq = node[i * 8 + 4]; }
    else        { v = node[i * 4 + 0]; tq = node[i * 4 + 2]; }

    const int*           maski = (const int*)maskp;
    const unsigned char* maskb = (const unsigned char*)maskp;
    int m32 = g_mask32;

    const __half2* qrow = reinterpret_cast<const __half2*>(&g_tabQ_h[(size_t)v * 128]);
    float2 qa = __half22float2(qrow[l]);       // head0 chans 2l, 2l+1
    float2 qb = __half22float2(qrow[32 + l]);  // head1 chans 64+2l, 64+2l+1

    float2 o0 = make_float2(0.f, 0.f), o1 = make_float2(0.f, 0.f);
    int unm = 0;

    for (int j = w; j < NBRS; j += 4) {
        int eb = (i * NBRS + j) * 3;
        int nv = nbr[eb], nr = nbr[eb + 1], nt = nbr[eb + 2];
        int m  = m32 ? maski[i * NBRS + j] : (int)maskb[i * NBRS + j];
        int di = tq - nt + DT_OFF;
        di = min(max(di, 0), DT_ROWS - 1);
        const __half2* pv = reinterpret_cast<const __half2*>(&g_tabKVv_h[(size_t)nv * 256]);
        const __half2* pr = reinterpret_cast<const __half2*>(&g_tabKVr_h[(size_t)nr * 256]);
        const __half2* pt = reinterpret_cast<const __half2*>(&g_tabKVt_h[(size_t)di * 256]);

        float2 k0 = sum3h(pv[l     ], pr[l     ], pt[l     ]);
        float2 k1 = sum3h(pv[32 + l], pr[32 + l], pt[32 + l]);
        float2 v0 = sum3h(pv[64 + l], pr[64 + l], pt[64 + l]);
        float2 v1 = sum3h(pv[96 + l], pr[96 + l], pt[96 + l]);

        float p0 = qa.x * k0.x + qa.y * k0.y;   // head 0 partial
        float p1 = qb.x * k1.x + qb.y * k1.y;   // head 1 partial
#pragma unroll
        for (int off = 16; off; off >>= 1) {
            p0 += __shfl_xor_sync(0xffffffffu, p0, off);
            p1 += __shfl_xor_sync(0xffffffffu, p1, off);
        }
        float a0, a1;
        if (m) { a0 = 0.5f; a1 = 0.5f; }     // masked: softmax over 2 equal -> (.5,.5)
        else {
            const float sc = 0.08838834764831843f;  // 1/sqrt(128)
            float s0 = p0 * sc, s1 = p1 * sc;
            float mx = fmaxf(s0, s1);
            float e0 = expf(s0 - mx), e1 = expf(s1 - mx);
            float inv = 1.0f / (e0 + e1);
            a0 = e0 * inv; a1 = e1 * inv;
            unm++;
        }
        o0.x += a0 * v0.x; o0.y += a0 * v0.y;
        o1.x += a1 * v1.x; o1.y += a1 * v1.y;
    }

    sPart[w][2*l] = o0.x; sPart[w][2*l+1] = o0.y;
    sPart[w][64+2*l] = o1.x; sPart[w][64+2*l+1] = o1.y;
    if (l == 0) sUnm[w] = unm;
    __syncthreads();
    int tot = sUnm[0] + sUnm[1] + sUnm[2] + sUnm[3];

    float f0 = sPart[0][l     ] + sPart[1][l     ] + sPart[2][l     ] + sPart[3][l     ];
    float f1 = sPart[0][l + 32] + sPart[1][l + 32] + sPart[2][l + 32] + sPart[3][l + 32];
    float f2 = sPart[0][l + 64] + sPart[1][l + 64] + sPart[2][l + 64] + sPart[3][l + 64];
    float f3 = sPart[0][l + 96] + sPart[1][l + 96] + sPart[2][l + 96] + sPart[3][l + 96];

    for (int c = w; c < NCLS; c += 4) {
        const float* wr = &g_Wco[c * 128];
        float p = wr[l] * f0 + wr[l + 32] * f1 + wr[l + 64] * f2 + wr[l + 96] * f3;
#pragma unroll
        for (int off = 16; off; off >>= 1) p += __shfl_xor_sync(0xffffffffu, p, off);
        if (l == 0) out[(size_t)i * NCLS + c] = (tot == 0) ? bc[c] : (g_bco[c] + p);
    }
}

// ---------------- launch ------------------------------------------------------
extern "C" void kernel_launch(void* const* d_in, const int* in_sizes, int n_in,
                              void* d_out, int out_size)
{
    const int*   node  = (const int*)d_in[0];
    const int*   nbr   = (const int*)d_in[1];
    const void*  mask  = d_in[2];
    const float* v_emb = (const float*)d_in[3];
    const float* r_emb = (const float*)d_in[4];
    const float* tw    = (const float*)d_in[5];
    const float* tb    = (const float*)d_in[6];
    const float* Wq    = (const float*)d_in[7];
    const float* bq    = (const float*)d_in[8];
    const float* Wk    = (const float*)d_in[9];
    const float* bk    = (const float*)d_in[10];
    const float* Wv    = (const float*)d_in[11];
    const float* bv    = (const float*)d_in[12];
    const float* Wo    = (const float*)d_in[13];
    const float* bo    = (const float*)d_in[14];
    const float* Wc    = (const float*)d_in[15];
    const float* bc    = (const float*)d_in[16];
    float* out = (float*)d_out;

    int N  = in_sizes[0] / 4;
    int Mv = in_sizes[3] / 128;
    int Mr = in_sizes[4] / 128;

    tgn_detect_node<<<1, 256>>>(node, in_sizes[0]);
    tgn_detect_mask<<<1, 256>>>((const unsigned char*)mask, in_sizes[2]);

    tgn_prep<<<1, 128>>>(Wq, bq, Wk, Wv, Wo, bo, Wc, bc, tb);

    Slice3 Pv;
    Pv.s[0] = { Wq,       256, 0, 128,   0, 1 };
    Pv.s[1] = { Wk,       384, 1, 256,   0, 0 };
    Pv.s[2] = { Wv,       384, 1, 256, 128, 0 };
    dim3 g1((Mv + 127) / 128, 3);
    tgn_gemm<<<g1, 256>>>(v_emb, Mv, Pv);

    Slice3 Pr;
    Pr.s[0] = { Wk + 128, 384, 2, 256,   0, 0 };
    Pr.s[1] = { Wv + 128, 384, 2, 256, 128, 0 };
    Pr.s[2] = Pr.s[0];
    dim3 g2((Mr + 127) / 128, 2);
    tgn_gemm<<<g2, 256>>>(r_emb, Mr, Pr);

    tgn_dt<<<(DT_ROWS + 7) / 8, 256>>>(bk, bv, tw, tb);

    tgn_attn<<<N, 128>>>(node, nbr, mask, bc, out, N);
}

// round 8
// speedup vs baseline: 1.4988x; 1.2029x over previous
#include <cuda_runtime.h>
#include <cuda_fp16.h>
#include <cstdint>
#include <math.h>

#define V_NUM   100000
#define R_NUM   100000
#define NBRS    20
#define NCLS    10
#define DT_ROWS 200004
#define DT_OFF  100000

// ---------------- scratch tables (device globals) ---------------------------
__device__ __half g_tabQ_h  [(size_t)V_NUM * 128];   //  25.6 MB
__device__ __half g_tabKVv_h[(size_t)V_NUM * 256];   //  51.2 MB
__device__ __half g_tabKVr_h[(size_t)R_NUM * 256];   //  51.2 MB
__device__ __half g_tabKVt_h[(size_t)DT_ROWS * 256]; // 102.4 MB
__device__ float  g_E       [(size_t)DT_ROWS * 128]; // 102.4 MB cos matrix
__device__ float g_qcb [128];
__device__ float g_Wco [NCLS * 128];              // Wc @ Wo
__device__ float g_bco [NCLS];                    // Wc @ bo + bc
__device__ int   g_is64;                          // node_data dtype flag
__device__ int   g_mask32;                        // nbr_mask dtype flag

// Accurate, fast cosine independent of -use_fast_math:
// quadrant reduction with one DP FMA (exact), then minimax polys on [-pi/4,pi/4].
__device__ __forceinline__ float cosq(float x)
{
    float kf = rintf(x * 0.6366197723675814f);        // x * 2/pi
    int   k  = (int)kf;
    double rd = fma((double)kf, -1.5707963267948966, (double)x);
    float r  = (float)rd;
    float r2 = r * r;
    float c = fmaf(r2, fmaf(r2, fmaf(r2, fmaf(r2, 2.47959626e-5f, -1.38888876e-3f),
                                      4.16666418e-2f), -4.99999970e-1f), 1.0f);
    float s = r * fmaf(r2, fmaf(r2, fmaf(r2, -1.95152959e-4f, 8.33216087e-3f),
                                 -1.66666546e-1f), 1.0f);
    int q = k & 3;
    float res = (q & 1) ? s : c;
    return ((q == 1) || (q == 2)) ? -res : res;
}

__device__ __forceinline__ float2 sum3h(__half2 a, __half2 b, __half2 c)
{
    float2 x = __half22float2(a), y = __half22float2(b), z = __half22float2(c);
    return make_float2(x.x + y.x + z.x, x.y + y.y + z.y);
}

__device__ __forceinline__ uint32_t f2tf32(float f)
{
    uint32_t u;
    asm("cvt.rna.tf32.f32 %0, %1;" : "=r"(u) : "f"(f));
    return u;
}

__device__ __forceinline__ void mma8(float* d, const uint32_t* a, uint32_t b0, uint32_t b1)
{
    asm volatile(
        "mma.sync.aligned.m16n8k8.row.col.f32.tf32.tf32.f32 "
        "{%0,%1,%2,%3},{%4,%5,%6,%7},{%8,%9},{%0,%1,%2,%3};"
        : "+f"(d[0]), "+f"(d[1]), "+f"(d[2]), "+f"(d[3])
        : "r"(a[0]), "r"(a[1]), "r"(a[2]), "r"(a[3]), "r"(b0), "r"(b1));
}

// ---------------- dtype detects ----------------------------------------------
__global__ void tgn_detect_node(const int* __restrict__ node, int n_words)
{
    __shared__ int sOr[256];
    int t = threadIdx.x;
    int acc = 0;
    for (int i = 1 + 2 * t; i < n_words; i += 512) acc |= node[i];
    sOr[t] = acc;
    __syncthreads();
    for (int s = 128; s; s >>= 1) { if (t < s) sOr[t] |= sOr[t + s]; __syncthreads(); }
    if (t == 0) g_is64 = (sOr[0] == 0) ? 1 : 0;
}

__global__ void tgn_detect_mask(const unsigned char* __restrict__ m, int n_elems)
{
    __shared__ int sOr[256];
    int t = threadIdx.x;
    int acc = 0;
    for (int i = t; i < n_elems; i += 256)
        if (i & 3) acc |= m[i];
    sOr[t] = acc;
    __syncthreads();
    for (int s = 128; s; s >>= 1) { if (t < s) sOr[t] |= sOr[t + s]; __syncthreads(); }
    if (t == 0) g_mask32 = (sOr[0] == 0) ? 1 : 0;
}

// ---------------- prep: small constants --------------------------------------
__global__ void tgn_prep(const float* __restrict__ Wq, const float* __restrict__ bq,
                         const float* __restrict__ Wo, const float* __restrict__ bo,
                         const float* __restrict__ Wc, const float* __restrict__ bc,
                         const float* __restrict__ tb)
{
    int t = threadIdx.x;  // 128 threads
    float acc = bq[t];
    for (int c = 0; c < 128; ++c) acc += Wq[t * 256 + 128 + c] * cosq(tb[c]);
    g_qcb[t] = acc;
    for (int c = 0; c < NCLS; ++c) {
        float s = 0.f;
        for (int m = 0; m < 128; ++m) s += Wc[c * 128 + m] * Wo[m * 128 + t];
        g_Wco[c * 128 + t] = s;
    }
    if (t < NCLS) {
        float s = bc[t];
        for (int m = 0; m < 128; ++m) s += Wc[t * 128 + m] * bo[m];
        g_bco[t] = s;
    }
}

// ---------------- cos matrix E[dt][c] = cos(fl(d*w_c) + b_c) ------------------
__global__ void tgn_cosE(const float* __restrict__ tw, const float* __restrict__ tb)
{
    long idx = (long)blockIdx.x * 256 + threadIdx.x;
    long row = idx >> 7;
    if (row >= DT_ROWS) return;
    int  c = (int)(idx & 127);
    float dv = (float)(row - DT_OFF);
    float x  = __fadd_rn(__fmul_rn(dv, tw[c]), tb[c]);   // match reference rounding
    g_E[idx] = cosq(x);
}

// ---------------- unified tf32 MMA table GEMM --------------------------------
// C[m0:m0+128, cofs:cofs+128] (fp16 table) = A[m0:m0+128, 0:128] @ W_slice^T + bias
struct TSlice  { const float* W; const float* bias; int ldw; int tab; int ldc; int cofs; int qcb; };
struct TSlice3 { TSlice s[3]; };

__global__ __launch_bounds__(256)
void tgn_mma(const float* __restrict__ Ain, int M, TSlice3 P)
{
    __shared__ uint32_t As[128][36];
    __shared__ uint32_t Bs[128][36];
    TSlice sl = P.s[blockIdx.y];
    const float* A = Ain ? Ain : (const float*)g_E;
    __half* C = (sl.tab == 0) ? g_tabQ_h : (sl.tab == 1) ? g_tabKVv_h
              : (sl.tab == 2) ? g_tabKVr_h : g_tabKVt_h;
    const float* bias = sl.qcb ? g_qcb : sl.bias;

    int m0   = blockIdx.x * 128;
    int tid  = threadIdx.x;
    int warp = tid >> 5, lane = tid & 31;
    int wm = warp >> 2, wn = warp & 3;       // warp grid 2 (m) x 4 (n)
    int g  = lane >> 2, t4 = lane & 3;

    float acc[4][4][4];
#pragma unroll
    for (int a = 0; a < 4; ++a)
#pragma unroll
        for (int b = 0; b < 4; ++b)
#pragma unroll
            for (int d = 0; d < 4; ++d) acc[a][b][d] = 0.f;

    for (int kc = 0; kc < 128; kc += 32) {
        __syncthreads();
#pragma unroll
        for (int it = 0; it < 4; ++it) {
            int idx = tid + it * 256;        // 0..1023
            int r   = idx >> 3;
            int c4  = (idx & 7) * 4;
            float4 av = make_float4(0.f, 0.f, 0.f, 0.f);
            if (m0 + r < M)
                av = *reinterpret_cast<const float4*>(&A[(size_t)(m0 + r) * 128 + kc + c4]);
            As[r][c4 + 0] = f2tf32(av.x); As[r][c4 + 1] = f2tf32(av.y);
            As[r][c4 + 2] = f2tf32(av.z); As[r][c4 + 3] = f2tf32(av.w);
            float4 bv = *reinterpret_cast<const float4*>(&sl.W[(size_t)r * sl.ldw + kc + c4]);
            Bs[r][c4 + 0] = f2tf32(bv.x); Bs[r][c4 + 1] = f2tf32(bv.y);
            Bs[r][c4 + 2] = f2tf32(bv.z); Bs[r][c4 + 3] = f2tf32(bv.w);
        }
        __syncthreads();
#pragma unroll
        for (int ks = 0; ks < 4; ++ks) {
            int k0 = ks * 8;
            uint32_t af[4][4];
#pragma unroll
            for (int mt = 0; mt < 4; ++mt) {
                int rm = wm * 64 + mt * 16;
                af[mt][0] = As[rm + g    ][k0 + t4];
                af[mt][1] = As[rm + g + 8][k0 + t4];
                af[mt][2] = As[rm + g    ][k0 + t4 + 4];
                af[mt][3] = As[rm + g + 8][k0 + t4 + 4];
            }
#pragma unroll
            for (int nt = 0; nt < 4; ++nt) {
                int nb = wn * 32 + nt * 8;
                uint32_t b0 = Bs[nb + g][k0 + t4];
                uint32_t b1 = Bs[nb + g][k0 + t4 + 4];
#pragma unroll
                for (int mt = 0; mt < 4; ++mt)
                    mma8(acc[mt][nt], af[mt], b0, b1);
            }
        }
    }

    // epilogue: bias add, fp16 convert, half2 stores
#pragma unroll
    for (int nt = 0; nt < 4; ++nt) {
        int lc = wn * 32 + nt * 8 + 2 * t4;          // 0..127 (slice-local col)
        float b0v = bias ? bias[lc]     : 0.f;
        float b1v = bias ? bias[lc + 1] : 0.f;
#pragma unroll
        for (int mt = 0; mt < 4; ++mt) {
            int r0 = m0 + wm * 64 + mt * 16 + g;
            int r1 = r0 + 8;
            if (r0 < M) {
                __half2 h = __floats2half2_rn(acc[mt][nt][0] + b0v, acc[mt][nt][1] + b1v);
                *reinterpret_cast<__half2*>(&C[(size_t)r0 * sl.ldc + sl.cofs + lc]) = h;
            }
            if (r1 < M) {
                __half2 h = __floats2half2_rn(acc[mt][nt][2] + b0v, acc[mt][nt][3] + b1v);
                *reinterpret_cast<__half2*>(&C[(size_t)r1 * sl.ldc + sl.cofs + lc]) = h;
            }
        }
    }
}

// ---------------- attention + epilogue: one block (128 thr) per node --------
__global__ void tgn_attn(const int* __restrict__ node, const int* __restrict__ nbr,
                         const void* __restrict__ maskp,
                         const float* __restrict__ bc,
                         float* __restrict__ out, int N)
{
    int i = blockIdx.x;
    if (i >= N) return;
    int tid = threadIdx.x, w = tid >> 5, l = tid & 31;
    __shared__ float sPart[4][128];
    __shared__ int   sUnm[4];

    int v, tq;
    if (g_is64) { v = node[i * 8 + 0]; tq = node[i * 8 + 4]; }
    else        { v = node[i * 4 + 0]; tq = node[i * 4 + 2]; }

    const int*           maski = (const int*)maskp;
    const unsigned char* maskb = (const unsigned char*)maskp;
    int m32 = g_mask32;

    const __half2* qrow = reinterpret_cast<const __half2*>(&g_tabQ_h[(size_t)v * 128]);
    float2 qa = __half22float2(qrow[l]);
    float2 qb = __half22float2(qrow[32 + l]);

    // preload this warp's 5 edge index tuples
    int nvv[5], nrr[5], dii[5], mk[5];
#pragma unroll
    for (int s = 0; s < 5; ++s) {
        int j  = w + s * 4;
        int eb = (i * NBRS + j) * 3;
        nvv[s] = nbr[eb];
        nrr[s] = nbr[eb + 1];
        int nt = nbr[eb + 2];
        mk[s]  = m32 ? maski[i * NBRS + j] : (int)maskb[i * NBRS + j];
        int di = tq - nt + DT_OFF;
        dii[s] = min(max(di, 0), DT_ROWS - 1);
    }

    float2 o0 = make_float2(0.f, 0.f), o1 = make_float2(0.f, 0.f);
    int unm = 0;

    __half2 buf[2][12];
#define LOAD_EDGE(s, b)                                                            \
    {                                                                              \
        const __half2* v2 = reinterpret_cast<const __half2*>(&g_tabKVv_h[(size_t)nvv[s] * 256]); \
        const __half2* r2 = reinterpret_cast<const __half2*>(&g_tabKVr_h[(size_t)nrr[s] * 256]); \
        const __half2* t2 = reinterpret_cast<const __half2*>(&g_tabKVt_h[(size_t)dii[s] * 256]); \
        b[0] = v2[l]; b[1] = v2[32 + l]; b[2] = v2[64 + l]; b[3] = v2[96 + l];     \
        b[4] = r2[l]; b[5] = r2[32 + l]; b[6] = r2[64 + l]; b[7] = r2[96 + l];     \
        b[8] = t2[l]; b[9] = t2[32 + l]; b[10] = t2[64 + l]; b[11] = t2[96 + l];   \
    }

    LOAD_EDGE(0, buf[0]);
#pragma unroll
    for (int s = 0; s < 5; ++s) {
        if (s < 4) LOAD_EDGE(s + 1, buf[(s + 1) & 1]);
        __half2* b = buf[s & 1];
        float2 k0 = sum3h(b[0], b[4], b[8]);
        float2 k1 = sum3h(b[1], b[5], b[9]);
        float2 v0 = sum3h(b[2], b[6], b[10]);
        float2 v1 = sum3h(b[3], b[7], b[11]);

        float p0 = qa.x * k0.x + qa.y * k0.y;
        float p1 = qb.x * k1.x + qb.y * k1.y;
#pragma unroll
        for (int off = 16; off; off >>= 1) {
            p0 += __shfl_xor_sync(0xffffffffu, p0, off);
            p1 += __shfl_xor_sync(0xffffffffu, p1, off);
        }
        float a0, a1;
        if (mk[s]) { a0 = 0.5f; a1 = 0.5f; }
        else {
            const float sc = 0.08838834764831843f;  // 1/sqrt(128)
            float s0 = p0 * sc, s1 = p1 * sc;
            float mx = fmaxf(s0, s1);
            float e0 = expf(s0 - mx), e1 = expf(s1 - mx);
            float inv = 1.0f / (e0 + e1);
            a0 = e0 * inv; a1 = e1 * inv;
            unm++;
        }
        o0.x += a0 * v0.x; o0.y += a0 * v0.y;
        o1.x += a1 * v1.x; o1.y += a1 * v1.y;
    }
#undef LOAD_EDGE

    sPart[w][2 * l] = o0.x; sPart[w][2 * l + 1] = o0.y;
    sPart[w][64 + 2 * l] = o1.x; sPart[w][64 + 2 * l + 1] = o1.y;
    if (l == 0) sUnm[w] = unm;
    __syncthreads();
    int tot = sUnm[0] + sUnm[1] + sUnm[2] + sUnm[3];

    float f0 = sPart[0][l     ] + sPart[1][l     ] + sPart[2][l     ] + sPart[3][l     ];
    float f1 = sPart[0][l + 32] + sPart[1][l + 32] + sPart[2][l + 32] + sPart[3][l + 32];
    float f2 = sPart[0][l + 64] + sPart[1][l + 64] + sPart[2][l + 64] + sPart[3][l + 64];
    float f3 = sPart[0][l + 96] + sPart[1][l + 96] + sPart[2][l + 96] + sPart[3][l + 96];

    for (int c = w; c < NCLS; c += 4) {
        const float* wr = &g_Wco[c * 128];
        float p = wr[l] * f0 + wr[l + 32] * f1 + wr[l + 64] * f2 + wr[l + 96] * f3;
#pragma unroll
        for (int off = 16; off; off >>= 1) p += __shfl_xor_sync(0xffffffffu, p, off);
        if (l == 0) out[(size_t)i * NCLS + c] = (tot == 0) ? bc[c] : (g_bco[c] + p);
    }
}

// ---------------- launch ------------------------------------------------------
extern "C" void kernel_launch(void* const* d_in, const int* in_sizes, int n_in,
                              void* d_out, int out_size)
{
    const int*   node  = (const int*)d_in[0];
    const int*   nbr   = (const int*)d_in[1];
    const void*  mask  = d_in[2];
    const float* v_emb = (const float*)d_in[3];
    const float* r_emb = (const float*)d_in[4];
    const float* tw    = (const float*)d_in[5];
    const float* tb    = (const float*)d_in[6];
    const float* Wq    = (const float*)d_in[7];
    const float* bq    = (const float*)d_in[8];
    const float* Wk    = (const float*)d_in[9];
    const float* bk    = (const float*)d_in[10];
    const float* Wv    = (const float*)d_in[11];
    const float* bv    = (const float*)d_in[12];
    const float* Wo    = (const float*)d_in[13];
    const float* bo    = (const float*)d_in[14];
    const float* Wc    = (const float*)d_in[15];
    const float* bc    = (const float*)d_in[16];
    float* out = (float*)d_out;

    int N  = in_sizes[0] / 4;
    int Mv = in_sizes[3] / 128;
    int Mr = in_sizes[4] / 128;

    tgn_detect_node<<<1, 256>>>(node, in_sizes[0]);
    tgn_detect_mask<<<1, 256>>>((const unsigned char*)mask, in_sizes[2]);

    tgn_prep<<<1, 128>>>(Wq, bq, Wo, bo, Wc, bc, tb);

    tgn_cosE<<<(int)(((long)DT_ROWS * 128 + 255) / 256), 256>>>(tw, tb);

    TSlice3 Pv;
    Pv.s[0] = { Wq,       nullptr, 256, 0, 128,   0, 1 };
    Pv.s[1] = { Wk,       nullptr, 384, 1, 256,   0, 0 };
    Pv.s[2] = { Wv,       nullptr, 384, 1, 256, 128, 0 };
    tgn_mma<<<dim3((Mv + 127) / 128, 3), 256>>>(v_emb, Mv, Pv);

    TSlice3 Pr;
    Pr.s[0] = { Wk + 128, nullptr, 384, 2, 256,   0, 0 };
    Pr.s[1] = { Wv + 128, nullptr, 384, 2, 256, 128, 0 };
    Pr.s[2] = Pr.s[0];
    tgn_mma<<<dim3((Mr + 127) / 128, 2), 256>>>(r_emb, Mr, Pr);

    TSlice3 Pt;
    Pt.s[0] = { Wk + 256, bk,      384, 3, 256,   0, 0 };
    Pt.s[1] = { Wv + 256, bv,      384, 3, 256, 128, 0 };
    Pt.s[2] = Pt.s[0];
    tgn_mma<<<dim3((DT_ROWS + 127) / 128, 2), 256>>>(nullptr, DT_ROWS, Pt);

    tgn_attn<<<N, 128>>>(node, nbr, mask, bc, out, N);
}

// round 10
// speedup vs baseline: 1.5731x; 1.0496x over previous
#include <cuda_runtime.h>
#include <cuda_fp16.h>
#include <cstdint>
#include <math.h>

#define V_NUM   100000
#define R_NUM   100000
#define NBRS    20
#define NCLS    10
#define DT_ROWS 200004
#define DT_OFF  100000

// ---------------- scratch tables (device globals) ---------------------------
__device__ __half g_tabQ_h  [(size_t)V_NUM * 128];   //  25.6 MB
__device__ __half g_tabKVv_h[(size_t)V_NUM * 256];   //  51.2 MB
__device__ __half g_tabKVr_h[(size_t)R_NUM * 256];   //  51.2 MB
__device__ __half g_tabKVt_h[(size_t)DT_ROWS * 256]; // 102.4 MB
__device__ float  g_E       [(size_t)DT_ROWS * 128]; // 102.4 MB cos matrix
__device__ float g_qcb [128];
__device__ float g_Wco [NCLS * 128];              // Wc @ Wo
__device__ float g_bco [NCLS];                    // Wc @ bo + bc
__device__ int   g_is64;                          // node_data dtype flag
__device__ int   g_mask32;                        // nbr_mask dtype flag

// Fast fp32 cosine with FMA Cody-Waite reduction (no DP, fast-math-proof).
// Valid for |x| < ~1e6 (kf < 2^24). Phase error ~1e-7.
__device__ __forceinline__ float cosq(float x)
{
    float kf = rintf(x * 0.6366197723675814f);        // x * 2/pi
    int   k  = (int)kf;
    float r  = fmaf(kf, -1.57079637050628662109375f, x);   // -C_hi (fp32 pi/2)
    r        = fmaf(kf,  4.37113900018624283e-8f,    r);   // -C_lo
    float r2 = r * r;
    float c = fmaf(r2, fmaf(r2, fmaf(r2, fmaf(r2, 2.47959626e-5f, -1.38888876e-3f),
                                      4.16666418e-2f), -4.99999970e-1f), 1.0f);
    float s = r * fmaf(r2, fmaf(r2, fmaf(r2, -1.95152959e-4f, 8.33216087e-3f),
                                 -1.66666546e-1f), 1.0f);
    int q = k & 3;
    float res = (q & 1) ? s : c;
    return ((q == 1) || (q == 2)) ? -res : res;
}

__device__ __forceinline__ uint32_t f2tf32(float f)
{
    uint32_t u;
    asm("cvt.rna.tf32.f32 %0, %1;" : "=r"(u) : "f"(f));
    return u;
}

__device__ __forceinline__ void mma8(float* d, const uint32_t* a, uint32_t b0, uint32_t b1)
{
    asm volatile(
        "mma.sync.aligned.m16n8k8.row.col.f32.tf32.tf32.f32 "
        "{%0,%1,%2,%3},{%4,%5,%6,%7},{%8,%9},{%0,%1,%2,%3};"
        : "+f"(d[0]), "+f"(d[1]), "+f"(d[2]), "+f"(d[3])
        : "r"(a[0]), "r"(a[1]), "r"(a[2]), "r"(a[3]), "r"(b0), "r"(b1));
}

// ---------------- dtype detects ----------------------------------------------
__global__ void tgn_detect_node(const int* __restrict__ node, int n_words)
{
    __shared__ int sOr[256];
    int t = threadIdx.x;
    int acc = 0;
    for (int i = 1 + 2 * t; i < n_words; i += 512) acc |= node[i];
    sOr[t] = acc;
    __syncthreads();
    for (int s = 128; s; s >>= 1) { if (t < s) sOr[t] |= sOr[t + s]; __syncthreads(); }
    if (t == 0) g_is64 = (sOr[0] == 0) ? 1 : 0;
}

__global__ void tgn_detect_mask(const unsigned char* __restrict__ m, int n_elems)
{
    __shared__ int sOr[256];
    int t = threadIdx.x;
    int acc = 0;
    for (int i = t; i < n_elems; i += 256)
        if (i & 3) acc |= m[i];
    sOr[t] = acc;
    __syncthreads();
    for (int s = 128; s; s >>= 1) { if (t < s) sOr[t] |= sOr[t + s]; __syncthreads(); }
    if (t == 0) g_mask32 = (sOr[0] == 0) ? 1 : 0;
}

// ---------------- prep: small constants --------------------------------------
__global__ void tgn_prep(const float* __restrict__ Wq, const float* __restrict__ bq,
                         const float* __restrict__ Wo, const float* __restrict__ bo,
                         const float* __restrict__ Wc, const float* __restrict__ bc,
                         const float* __restrict__ tb)
{
    int t = threadIdx.x;  // 128 threads
    float acc = bq[t];
    for (int c = 0; c < 128; ++c) acc += Wq[t * 256 + 128 + c] * cosq(tb[c]);
    g_qcb[t] = acc;
    for (int c = 0; c < NCLS; ++c) {
        float s = 0.f;
        for (int m = 0; m < 128; ++m) s += Wc[c * 128 + m] * Wo[m * 128 + t];
        g_Wco[c * 128 + t] = s;
    }
    if (t < NCLS) {
        float s = bc[t];
        for (int m = 0; m < 128; ++m) s += Wc[t * 128 + m] * bo[m];
        g_bco[t] = s;
    }
}

// ---------------- cos matrix E[dt][c] = cos(d*w_c + b_c), 4 chans/thread -----
__global__ void tgn_cosE(const float* __restrict__ tw, const float* __restrict__ tb)
{
    long idx = (long)blockIdx.x * 256 + threadIdx.x;   // DT_ROWS*32 threads
    long row = idx >> 5;
    if (row >= DT_ROWS) return;
    int  c4 = (int)(idx & 31) * 4;
    float dv = (float)(row - DT_OFF);
    float4 w = *reinterpret_cast<const float4*>(&tw[c4]);
    float4 b = *reinterpret_cast<const float4*>(&tb[c4]);
    float4 o;
    o.x = cosq(__fadd_rn(__fmul_rn(dv, w.x), b.x));
    o.y = cosq(__fadd_rn(__fmul_rn(dv, w.y), b.y));
    o.z = cosq(__fadd_rn(__fmul_rn(dv, w.z), b.z));
    o.w = cosq(__fadd_rn(__fmul_rn(dv, w.w), b.w));
    *reinterpret_cast<float4*>(&g_E[row * 128 + c4]) = o;
}

// ---------------- unified tf32 MMA table GEMM --------------------------------
struct TSlice  { const float* W; const float* bias; int ldw; int tab; int ldc; int cofs; int qcb; };
struct TSlice3 { TSlice s[3]; };

__global__ __launch_bounds__(256)
void tgn_mma(const float* __restrict__ Ain, int M, TSlice3 P)
{
    __shared__ uint32_t As[128][36];
    __shared__ uint32_t Bs[128][36];
    TSlice sl = P.s[blockIdx.y];
    const float* A = Ain ? Ain : (const float*)g_E;
    __half* C = (sl.tab == 0) ? g_tabQ_h : (sl.tab == 1) ? g_tabKVv_h
              : (sl.tab == 2) ? g_tabKVr_h : g_tabKVt_h;
    const float* bias = sl.qcb ? g_qcb : sl.bias;

    int m0   = blockIdx.x * 128;
    int tid  = threadIdx.x;
    int warp = tid >> 5, lane = tid & 31;
    int wm = warp >> 2, wn = warp & 3;
    int g  = lane >> 2, t4 = lane & 3;

    float acc[4][4][4];
#pragma unroll
    for (int a = 0; a < 4; ++a)
#pragma unroll
        for (int b = 0; b < 4; ++b)
#pragma unroll
            for (int d = 0; d < 4; ++d) acc[a][b][d] = 0.f;

    for (int kc = 0; kc < 128; kc += 32) {
        __syncthreads();
#pragma unroll
        for (int it = 0; it < 4; ++it) {
            int idx = tid + it * 256;
            int r   = idx >> 3;
            int c4  = (idx & 7) * 4;
            float4 av = make_float4(0.f, 0.f, 0.f, 0.f);
            if (m0 + r < M)
                av = *reinterpret_cast<const float4*>(&A[(size_t)(m0 + r) * 128 + kc + c4]);
            As[r][c4 + 0] = f2tf32(av.x); As[r][c4 + 1] = f2tf32(av.y);
            As[r][c4 + 2] = f2tf32(av.z); As[r][c4 + 3] = f2tf32(av.w);
            float4 bv = *reinterpret_cast<const float4*>(&sl.W[(size_t)r * sl.ldw + kc + c4]);
            Bs[r][c4 + 0] = f2tf32(bv.x); Bs[r][c4 + 1] = f2tf32(bv.y);
            Bs[r][c4 + 2] = f2tf32(bv.z); Bs[r][c4 + 3] = f2tf32(bv.w);
        }
        __syncthreads();
#pragma unroll
        for (int ks = 0; ks < 4; ++ks) {
            int k0 = ks * 8;
            uint32_t af[4][4];
#pragma unroll
            for (int mt = 0; mt < 4; ++mt) {
                int rm = wm * 64 + mt * 16;
                af[mt][0] = As[rm + g    ][k0 + t4];
                af[mt][1] = As[rm + g + 8][k0 + t4];
                af[mt][2] = As[rm + g    ][k0 + t4 + 4];
                af[mt][3] = As[rm + g + 8][k0 + t4 + 4];
            }
#pragma unroll
            for (int nt = 0; nt < 4; ++nt) {
                int nb = wn * 32 + nt * 8;
                uint32_t b0 = Bs[nb + g][k0 + t4];
                uint32_t b1 = Bs[nb + g][k0 + t4 + 4];
#pragma unroll
                for (int mt = 0; mt < 4; ++mt)
                    mma8(acc[mt][nt], af[mt], b0, b1);
            }
        }
    }

#pragma unroll
    for (int nt = 0; nt < 4; ++nt) {
        int lc = wn * 32 + nt * 8 + 2 * t4;
        float b0v = bias ? bias[lc]     : 0.f;
        float b1v = bias ? bias[lc + 1] : 0.f;
#pragma unroll
        for (int mt = 0; mt < 4; ++mt) {
            int r0 = m0 + wm * 64 + mt * 16 + g;
            int r1 = r0 + 8;
            if (r0 < M) {
                __half2 h = __floats2half2_rn(acc[mt][nt][0] + b0v, acc[mt][nt][1] + b1v);
                *reinterpret_cast<__half2*>(&C[(size_t)r0 * sl.ldc + sl.cofs + lc]) = h;
            }
            if (r1 < M) {
                __half2 h = __floats2half2_rn(acc[mt][nt][2] + b0v, acc[mt][nt][3] + b1v);
                *reinterpret_cast<__half2*>(&C[(size_t)r1 * sl.ldc + sl.cofs + lc]) = h;
            }
        }
    }
}

// ---------------- attention: uint4-per-lane layout ---------------------------
// Per edge: row = [K ch0..127 | V ch0..127] halfs (512B = 32 lanes x 16B).
// Lanes 0-15 own K (8 chans each), lanes 16-31 own V (8 chans each).
__global__ void tgn_attn(const int* __restrict__ node, const int* __restrict__ nbr,
                         const void* __restrict__ maskp,
                         const float* __restrict__ bc,
                         float* __restrict__ out, int N)
{
    int i = blockIdx.x;
    if (i >= N) return;
    int tid = threadIdx.x, w = tid >> 5, l = tid & 31;
    __shared__ float sPart[4][128];
    __shared__ float sF[128];
    __shared__ int   sUnm[4];

    int v, tq;
    if (g_is64) { v = node[i * 8 + 0]; tq = node[i * 8 + 4]; }
    else        { v = node[i * 4 + 0]; tq = node[i * 4 + 2]; }

    const int*           maski = (const int*)maskp;
    const unsigned char* maskb = (const unsigned char*)maskp;
    int m32 = g_mask32;

    // q fragment: lanes 0-15 hold channels 8l..8l+7
    float qf[8] = {0.f, 0.f, 0.f, 0.f, 0.f, 0.f, 0.f, 0.f};
    if (l < 16) {
        uint4 qv = *reinterpret_cast<const uint4*>(&g_tabQ_h[(size_t)v * 128 + l * 8]);
        __half2* qh = reinterpret_cast<__half2*>(&qv);
#pragma unroll
        for (int j = 0; j < 4; ++j) {
            float2 f = __half22float2(qh[j]);
            qf[2 * j] = f.x; qf[2 * j + 1] = f.y;
        }
    }

    // preload this warp's 5 edge tuples
    int nvv[5], nrr[5], dii[5], mk[5];
#pragma unroll
    for (int s = 0; s < 5; ++s) {
        int j  = w + s * 4;
        int eb = (i * NBRS + j) * 3;
        nvv[s] = nbr[eb];
        nrr[s] = nbr[eb + 1];
        int nt = nbr[eb + 2];
        mk[s]  = m32 ? maski[i * NBRS + j] : (int)maskb[i * NBRS + j];
        int di = tq - nt + DT_OFF;
        dii[s] = min(max(di, 0), DT_ROWS - 1);
    }

    float o[8] = {0.f, 0.f, 0.f, 0.f, 0.f, 0.f, 0.f, 0.f};
    int unm = 0;

    uint4 bv[2], br[2], bt[2];
#define LOAD_EDGE(s, b)                                                                          \
    {                                                                                            \
        bv[b] = *reinterpret_cast<const uint4*>(&g_tabKVv_h[(size_t)nvv[s] * 256 + l * 8]);      \
        br[b] = *reinterpret_cast<const uint4*>(&g_tabKVr_h[(size_t)nrr[s] * 256 + l * 8]);      \
        bt[b] = *reinterpret_cast<const uint4*>(&g_tabKVt_h[(size_t)dii[s] * 256 + l * 8]);      \
    }

    LOAD_EDGE(0, 0);
#pragma unroll
    for (int s = 0; s < 5; ++s) {
        if (s < 4) LOAD_EDGE(s + 1, (s + 1) & 1);
        int slot = s & 1;
        __half2* hv = reinterpret_cast<__half2*>(&bv[slot]);
        __half2* hr = reinterpret_cast<__half2*>(&br[slot]);
        __half2* ht = reinterpret_cast<__half2*>(&bt[slot]);
        float f3[8];
#pragma unroll
        for (int j = 0; j < 4; ++j) {
            float2 a = __half22float2(hv[j]);
            float2 b = __half22float2(hr[j]);
            float2 c = __half22float2(ht[j]);
            f3[2 * j]     = a.x + b.x + c.x;
            f3[2 * j + 1] = a.y + b.y + c.y;
        }
        // partial dot (k-lanes; v-lanes have qf = 0)
        float sp = qf[0] * f3[0] + qf[1] * f3[1] + qf[2] * f3[2] + qf[3] * f3[3]
                 + qf[4] * f3[4] + qf[5] * f3[5] + qf[6] * f3[6] + qf[7] * f3[7];
        sp += __shfl_xor_sync(0xffffffffu, sp, 1);
        sp += __shfl_xor_sync(0xffffffffu, sp, 2);
        sp += __shfl_xor_sync(0xffffffffu, sp, 4);
        float p0 = __shfl_sync(0xffffffffu, sp, 0);   // head 0 score*sqrt(128)
        float p1 = __shfl_sync(0xffffffffu, sp, 8);   // head 1
        float a0, a1;
        if (mk[s]) { a0 = 0.5f; a1 = 0.5f; }
        else {
            const float sc = 0.08838834764831843f;  // 1/sqrt(128)
            float s0 = p0 * sc, s1 = p1 * sc;
            float mx = fmaxf(s0, s1);
            float e0 = expf(s0 - mx), e1 = expf(s1 - mx);
            float inv = 1.0f / (e0 + e1);
            a0 = e0 * inv; a1 = e1 * inv;
            unm++;
        }
        float a = (l < 24) ? a0 : a1;
#pragma unroll
        for (int c = 0; c < 8; ++c) o[c] += a * f3[c];
    }
#undef LOAD_EDGE

    if (l >= 16) {
#pragma unroll
        for (int c = 0; c < 8; ++c) sPart[w][(l - 16) * 8 + c] = o[c];
    }
    if (l == 0) sUnm[w] = unm;
    __syncthreads();
    sF[tid] = sPart[0][tid] + sPart[1][tid] + sPart[2][tid] + sPart[3][tid];
    __syncthreads();
    int tot = sUnm[0] + sUnm[1] + sUnm[2] + sUnm[3];

    float f0 = sF[l], f1 = sF[l + 32], f2 = sF[l + 64], f3v = sF[l + 96];
    for (int c = w; c < NCLS; c += 4) {
        const float* wr = &g_Wco[c * 128];
        float p = wr[l] * f0 + wr[l + 32] * f1 + wr[l + 64] * f2 + wr[l + 96] * f3v;
#pragma unroll
        for (int off = 16; off; off >>= 1) p += __shfl_xor_sync(0xffffffffu, p, off);
        if (l == 0) out[(size_t)i * NCLS + c] = (tot == 0) ? bc[c] : (g_bco[c] + p);
    }
}

// ---------------- launch ------------------------------------------------------
extern "C" void kernel_launch(void* const* d_in, const int* in_sizes, int n_in,
                              void* d_out, int out_size)
{
    const int*   node  = (const int*)d_in[0];
    const int*   nbr   = (const int*)d_in[1];
    const void*  mask  = d_in[2];
    const float* v_emb = (const float*)d_in[3];
    const float* r_emb = (const float*)d_in[4];
    const float* tw    = (const float*)d_in[5];
    const float* tb    = (const float*)d_in[6];
    const float* Wq    = (const float*)d_in[7];
    const float* bq    = (const float*)d_in[8];
    const float* Wk    = (const float*)d_in[9];
    const float* bk    = (const float*)d_in[10];
    const float* Wv    = (const float*)d_in[11];
    const float* bv    = (const float*)d_in[12];
    const float* Wo    = (const float*)d_in[13];
    const float* bo    = (const float*)d_in[14];
    const float* Wc    = (const float*)d_in[15];
    const float* bc    = (const float*)d_in[16];
    float* out = (float*)d_out;

    int N  = in_sizes[0] / 4;
    int Mv = in_sizes[3] / 128;
    int Mr = in_sizes[4] / 128;

    tgn_detect_node<<<1, 256>>>(node, in_sizes[0]);
    tgn_detect_mask<<<1, 256>>>((const unsigned char*)mask, in_sizes[2]);

    tgn_prep<<<1, 128>>>(Wq, bq, Wo, bo, Wc, bc, tb);

    tgn_cosE<<<(int)(((long)DT_ROWS * 32 + 255) / 256), 256>>>(tw, tb);

    TSlice3 Pv;
    Pv.s[0] = { Wq,       nullptr, 256, 0, 128,   0, 1 };
    Pv.s[1] = { Wk,       nullptr, 384, 1, 256,   0, 0 };
    Pv.s[2] = { Wv,       nullptr, 384, 1, 256, 128, 0 };
    tgn_mma<<<dim3((Mv + 127) / 128, 3), 256>>>(v_emb, Mv, Pv);

    TSlice3 Pr;
    Pr.s[0] = { Wk + 128, nullptr, 384, 2, 256,   0, 0 };
    Pr.s[1] = { Wv + 128, nullptr, 384, 2, 256, 128, 0 };
    Pr.s[2] = Pr.s[0];
    tgn_mma<<<dim3((Mr + 127) / 128, 2), 256>>>(r_emb, Mr, Pr);

    TSlice3 Pt;
    Pt.s[0] = { Wk + 256, bk,      384, 3, 256,   0, 0 };
    Pt.s[1] = { Wv + 256, bv,      384, 3, 256, 128, 0 };
    Pt.s[2] = Pt.s[0];
    tgn_mma<<<dim3((DT_ROWS + 127) / 128, 2), 256>>>(nullptr, DT_ROWS, Pt);

    tgn_attn<<<N, 128>>>(node, nbr, mask, bc, out, N);
}

// round 11
// speedup vs baseline: 1.7224x; 1.0949x over previous
#include <cuda_runtime.h>
#include <cuda_fp16.h>
#include <cstdint>
#include <math.h>

#define V_NUM   100000
#define R_NUM   100000
#define NBRS    20
#define NCLS    10
#define DT_ROWS 200004
#define DT_OFF  100000

// ---------------- scratch tables (device globals) ---------------------------
__device__ __half g_tabQ_h  [(size_t)V_NUM * 128];   //  25.6 MB
__device__ __half g_tabKVv_h[(size_t)V_NUM * 256];   //  51.2 MB
__device__ __half g_tabKVr_h[(size_t)R_NUM * 256];   //  51.2 MB
__device__ __half g_tabKVt_h[(size_t)DT_ROWS * 256]; // 102.4 MB
__device__ float  g_E       [(size_t)DT_ROWS * 128]; // 102.4 MB cos matrix
__device__ float g_qcb [128];
__device__ float g_Wco [NCLS * 128];              // Wc @ Wo
__device__ float g_bco [NCLS];                    // Wc @ bo + bc
__device__ int   g_is64;                          // node_data dtype flag
__device__ int   g_mask32;                        // nbr_mask dtype flag

// Fast fp32 cosine with FMA Cody-Waite reduction (no DP, fast-math-proof).
__device__ __forceinline__ float cosq(float x)
{
    float kf = rintf(x * 0.6366197723675814f);        // x * 2/pi
    int   k  = (int)kf;
    float r  = fmaf(kf, -1.57079637050628662109375f, x);   // -C_hi (fp32 pi/2)
    r        = fmaf(kf,  4.37113900018624283e-8f,    r);   // -C_lo
    float r2 = r * r;
    float c = fmaf(r2, fmaf(r2, fmaf(r2, fmaf(r2, 2.47959626e-5f, -1.38888876e-3f),
                                      4.16666418e-2f), -4.99999970e-1f), 1.0f);
    float s = r * fmaf(r2, fmaf(r2, fmaf(r2, -1.95152959e-4f, 8.33216087e-3f),
                                 -1.66666546e-1f), 1.0f);
    int q = k & 3;
    float res = (q & 1) ? s : c;
    return ((q == 1) || (q == 2)) ? -res : res;
}

__device__ __forceinline__ uint32_t f2tf32(float f)
{
    uint32_t u;
    asm("cvt.rna.tf32.f32 %0, %1;" : "=r"(u) : "f"(f));
    return u;
}

__device__ __forceinline__ void mma8(float* d, const uint32_t* a, uint32_t b0, uint32_t b1)
{
    asm volatile(
        "mma.sync.aligned.m16n8k8.row.col.f32.tf32.tf32.f32 "
        "{%0,%1,%2,%3},{%4,%5,%6,%7},{%8,%9},{%0,%1,%2,%3};"
        : "+f"(d[0]), "+f"(d[1]), "+f"(d[2]), "+f"(d[3])
        : "r"(a[0]), "r"(a[1]), "r"(a[2]), "r"(a[3]), "r"(b0), "r"(b1));
}

// ---------------- dtype detects ----------------------------------------------
__global__ void tgn_detect_node(const int* __restrict__ node, int n_words)
{
    __shared__ int sOr[256];
    int t = threadIdx.x;
    int acc = 0;
    for (int i = 1 + 2 * t; i < n_words; i += 512) acc |= node[i];
    sOr[t] = acc;
    __syncthreads();
    for (int s = 128; s; s >>= 1) { if (t < s) sOr[t] |= sOr[t + s]; __syncthreads(); }
    if (t == 0) g_is64 = (sOr[0] == 0) ? 1 : 0;
}

__global__ void tgn_detect_mask(const unsigned char* __restrict__ m, int n_elems)
{
    __shared__ int sOr[256];
    int t = threadIdx.x;
    int acc = 0;
    for (int i = t; i < n_elems; i += 256)
        if (i & 3) acc |= m[i];
    sOr[t] = acc;
    __syncthreads();
    for (int s = 128; s; s >>= 1) { if (t < s) sOr[t] |= sOr[t + s]; __syncthreads(); }
    if (t == 0) g_mask32 = (sOr[0] == 0) ? 1 : 0;
}

// ---------------- prep: small constants --------------------------------------
__global__ void tgn_prep(const float* __restrict__ Wq, const float* __restrict__ bq,
                         const float* __restrict__ Wo, const float* __restrict__ bo,
                         const float* __restrict__ Wc, const float* __restrict__ bc,
                         const float* __restrict__ tb)
{
    int t = threadIdx.x;  // 128 threads
    float acc = bq[t];
    for (int c = 0; c < 128; ++c) acc += Wq[t * 256 + 128 + c] * cosq(tb[c]);
    g_qcb[t] = acc;
    for (int c = 0; c < NCLS; ++c) {
        float s = 0.f;
        for (int m = 0; m < 128; ++m) s += Wc[c * 128 + m] * Wo[m * 128 + t];
        g_Wco[c * 128 + t] = s;
    }
    if (t < NCLS) {
        float s = bc[t];
        for (int m = 0; m < 128; ++m) s += Wc[t * 128 + m] * bo[m];
        g_bco[t] = s;
    }
}

// ---------------- cos matrix E[dt][c] = cos(d*w_c + b_c), 4 chans/thread -----
__global__ void tgn_cosE(const float* __restrict__ tw, const float* __restrict__ tb)
{
    long idx = (long)blockIdx.x * 256 + threadIdx.x;
    long row = idx >> 5;
    if (row >= DT_ROWS) return;
    int  c4 = (int)(idx & 31) * 4;
    float dv = (float)(row - DT_OFF);
    float4 w = *reinterpret_cast<const float4*>(&tw[c4]);
    float4 b = *reinterpret_cast<const float4*>(&tb[c4]);
    float4 o;
    o.x = cosq(__fadd_rn(__fmul_rn(dv, w.x), b.x));
    o.y = cosq(__fadd_rn(__fmul_rn(dv, w.y), b.y));
    o.z = cosq(__fadd_rn(__fmul_rn(dv, w.z), b.z));
    o.w = cosq(__fadd_rn(__fmul_rn(dv, w.w), b.w));
    *reinterpret_cast<float4*>(&g_E[row * 128 + c4]) = o;
}

// ---------------- unified tf32 MMA table GEMM --------------------------------
struct TSlice  { const float* W; const float* bias; int ldw; int tab; int ldc; int cofs; int qcb; };
struct TSlice3 { TSlice s[3]; };

__global__ __launch_bounds__(256)
void tgn_mma(const float* __restrict__ Ain, int M, TSlice3 P)
{
    __shared__ uint32_t As[128][36];
    __shared__ uint32_t Bs[128][36];
    TSlice sl = P.s[blockIdx.y];
    const float* A = Ain ? Ain : (const float*)g_E;
    __half* C = (sl.tab == 0) ? g_tabQ_h : (sl.tab == 1) ? g_tabKVv_h
              : (sl.tab == 2) ? g_tabKVr_h : g_tabKVt_h;
    const float* bias = sl.qcb ? g_qcb : sl.bias;

    int m0   = blockIdx.x * 128;
    int tid  = threadIdx.x;
    int warp = tid >> 5, lane = tid & 31;
    int wm = warp >> 2, wn = warp & 3;
    int g  = lane >> 2, t4 = lane & 3;

    float acc[4][4][4];
#pragma unroll
    for (int a = 0; a < 4; ++a)
#pragma unroll
        for (int b = 0; b < 4; ++b)
#pragma unroll
            for (int d = 0; d < 4; ++d) acc[a][b][d] = 0.f;

    for (int kc = 0; kc < 128; kc += 32) {
        __syncthreads();
#pragma unroll
        for (int it = 0; it < 4; ++it) {
            int idx = tid + it * 256;
            int r   = idx >> 3;
            int c4  = (idx & 7) * 4;
            float4 av = make_float4(0.f, 0.f, 0.f, 0.f);
            if (m0 + r < M)
                av = *reinterpret_cast<const float4*>(&A[(size_t)(m0 + r) * 128 + kc + c4]);
            As[r][c4 + 0] = f2tf32(av.x); As[r][c4 + 1] = f2tf32(av.y);
            As[r][c4 + 2] = f2tf32(av.z); As[r][c4 + 3] = f2tf32(av.w);
            float4 bv = *reinterpret_cast<const float4*>(&sl.W[(size_t)r * sl.ldw + kc + c4]);
            Bs[r][c4 + 0] = f2tf32(bv.x); Bs[r][c4 + 1] = f2tf32(bv.y);
            Bs[r][c4 + 2] = f2tf32(bv.z); Bs[r][c4 + 3] = f2tf32(bv.w);
        }
        __syncthreads();
#pragma unroll
        for (int ks = 0; ks < 4; ++ks) {
            int k0 = ks * 8;
            uint32_t af[4][4];
#pragma unroll
            for (int mt = 0; mt < 4; ++mt) {
                int rm = wm * 64 + mt * 16;
                af[mt][0] = As[rm + g    ][k0 + t4];
                af[mt][1] = As[rm + g + 8][k0 + t4];
                af[mt][2] = As[rm + g    ][k0 + t4 + 4];
                af[mt][3] = As[rm + g + 8][k0 + t4 + 4];
            }
#pragma unroll
            for (int nt = 0; nt < 4; ++nt) {
                int nb = wn * 32 + nt * 8;
                uint32_t b0 = Bs[nb + g][k0 + t4];
                uint32_t b1 = Bs[nb + g][k0 + t4 + 4];
#pragma unroll
                for (int mt = 0; mt < 4; ++mt)
                    mma8(acc[mt][nt], af[mt], b0, b1);
            }
        }
    }

#pragma unroll
    for (int nt = 0; nt < 4; ++nt) {
        int lc = wn * 32 + nt * 8 + 2 * t4;
        float b0v = bias ? bias[lc]     : 0.f;
        float b1v = bias ? bias[lc + 1] : 0.f;
#pragma unroll
        for (int mt = 0; mt < 4; ++mt) {
            int r0 = m0 + wm * 64 + mt * 16 + g;
            int r1 = r0 + 8;
            if (r0 < M) {
                __half2 h = __floats2half2_rn(acc[mt][nt][0] + b0v, acc[mt][nt][1] + b1v);
                *reinterpret_cast<__half2*>(&C[(size_t)r0 * sl.ldc + sl.cofs + lc]) = h;
            }
            if (r1 < M) {
                __half2 h = __floats2half2_rn(acc[mt][nt][2] + b0v, acc[mt][nt][3] + b1v);
                *reinterpret_cast<__half2*>(&C[(size_t)r1 * sl.ldc + sl.cofs + lc]) = h;
            }
        }
    }
}

// ---------------- attention: full prefetch (15 outstanding LDG.128 per lane) -
// Per edge row: [K ch0..127 | V ch0..127] halfs (512B = 32 lanes x 16B).
// Lanes 0-15 own K (8 chans each), lanes 16-31 own V (8 chans each).
__global__ __launch_bounds__(128)
void tgn_attn(const int* __restrict__ node, const int* __restrict__ nbr,
              const void* __restrict__ maskp,
              const float* __restrict__ bc,
              float* __restrict__ out, int N)
{
    int i = blockIdx.x;
    if (i >= N) return;
    int tid = threadIdx.x, w = tid >> 5, l = tid & 31;
    __shared__ float sPart[4][128];
    __shared__ float sF[128];
    __shared__ int   sUnm[4];

    int v, tq;
    if (g_is64) { v = node[i * 8 + 0]; tq = node[i * 8 + 4]; }
    else        { v = node[i * 4 + 0]; tq = node[i * 4 + 2]; }

    const int*           maski = (const int*)maskp;
    const unsigned char* maskb = (const unsigned char*)maskp;
    int m32 = g_mask32;

    // edge tuples for this warp (5 edges)
    int nvv[5], nrr[5], dii[5], mk[5];
#pragma unroll
    for (int s = 0; s < 5; ++s) {
        int j  = w + s * 4;
        int eb = (i * NBRS + j) * 3;
        nvv[s] = nbr[eb];
        nrr[s] = nbr[eb + 1];
        int nt = nbr[eb + 2];
        mk[s]  = m32 ? maski[i * NBRS + j] : (int)maskb[i * NBRS + j];
        int di = tq - nt + DT_OFF;
        dii[s] = min(max(di, 0), DT_ROWS - 1);
    }

    // issue ALL 15 gathers + q load up front (independent -> front-batched LDGs)
    uint4 bv[5], br[5], bt[5];
#pragma unroll
    for (int s = 0; s < 5; ++s) {
        bv[s] = *reinterpret_cast<const uint4*>(&g_tabKVv_h[(size_t)nvv[s] * 256 + l * 8]);
        br[s] = *reinterpret_cast<const uint4*>(&g_tabKVr_h[(size_t)nrr[s] * 256 + l * 8]);
        bt[s] = *reinterpret_cast<const uint4*>(&g_tabKVt_h[(size_t)dii[s] * 256 + l * 8]);
    }

    // q fragment: lanes 0-15 hold channels 8l..8l+7
    float qf[8] = {0.f, 0.f, 0.f, 0.f, 0.f, 0.f, 0.f, 0.f};
    if (l < 16) {
        uint4 qv = *reinterpret_cast<const uint4*>(&g_tabQ_h[(size_t)v * 128 + l * 8]);
        __half2* qh = reinterpret_cast<__half2*>(&qv);
#pragma unroll
        for (int j = 0; j < 4; ++j) {
            float2 f = __half22float2(qh[j]);
            qf[2 * j] = f.x; qf[2 * j + 1] = f.y;
        }
    }

    float o[8] = {0.f, 0.f, 0.f, 0.f, 0.f, 0.f, 0.f, 0.f};
    int unm = 0;

#pragma unroll
    for (int s = 0; s < 5; ++s) {
        __half2* hv = reinterpret_cast<__half2*>(&bv[s]);
        __half2* hr = reinterpret_cast<__half2*>(&br[s]);
        __half2* ht = reinterpret_cast<__half2*>(&bt[s]);
        float f3[8];
#pragma unroll
        for (int j = 0; j < 4; ++j) {
            float2 a = __half22float2(hv[j]);
            float2 b = __half22float2(hr[j]);
            float2 c = __half22float2(ht[j]);
            f3[2 * j]     = a.x + b.x + c.x;
            f3[2 * j + 1] = a.y + b.y + c.y;
        }
        float sp = qf[0] * f3[0] + qf[1] * f3[1] + qf[2] * f3[2] + qf[3] * f3[3]
                 + qf[4] * f3[4] + qf[5] * f3[5] + qf[6] * f3[6] + qf[7] * f3[7];
        sp += __shfl_xor_sync(0xffffffffu, sp, 1);
        sp += __shfl_xor_sync(0xffffffffu, sp, 2);
        sp += __shfl_xor_sync(0xffffffffu, sp, 4);
        float p0 = __shfl_sync(0xffffffffu, sp, 0);   // head 0 score * sqrt(128)
        float p1 = __shfl_sync(0xffffffffu, sp, 8);   // head 1
        float a0, a1;
        if (mk[s]) { a0 = 0.5f; a1 = 0.5f; }
        else {
            const float sc = 0.08838834764831843f;  // 1/sqrt(128)
            float s0 = p0 * sc, s1 = p1 * sc;
            float mx = fmaxf(s0, s1);
            float e0 = expf(s0 - mx), e1 = expf(s1 - mx);
            float inv = 1.0f / (e0 + e1);
            a0 = e0 * inv; a1 = e1 * inv;
            unm++;
        }
        float a = (l < 24) ? a0 : a1;
#pragma unroll
        for (int c = 0; c < 8; ++c) o[c] += a * f3[c];
    }

    if (l >= 16) {
#pragma unroll
        for (int c = 0; c < 8; ++c) sPart[w][(l - 16) * 8 + c] = o[c];
    }
    if (l == 0) sUnm[w] = unm;
    __syncthreads();
    sF[tid] = sPart[0][tid] + sPart[1][tid] + sPart[2][tid] + sPart[3][tid];
    __syncthreads();
    int tot = sUnm[0] + sUnm[1] + sUnm[2] + sUnm[3];

    float f0 = sF[l], f1 = sF[l + 32], f2 = sF[l + 64], f3v = sF[l + 96];
    for (int c = w; c < NCLS; c += 4) {
        const float* wr = &g_Wco[c * 128];
        float p = wr[l] * f0 + wr[l + 32] * f1 + wr[l + 64] * f2 + wr[l + 96] * f3v;
#pragma unroll
        for (int off = 16; off; off >>= 1) p += __shfl_xor_sync(0xffffffffu, p, off);
        if (l == 0) out[(size_t)i * NCLS + c] = (tot == 0) ? bc[c] : (g_bco[c] + p);
    }
}

// ---------------- launch ------------------------------------------------------
extern "C" void kernel_launch(void* const* d_in, const int* in_sizes, int n_in,
                              void* d_out, int out_size)
{
    const int*   node  = (const int*)d_in[0];
    const int*   nbr   = (const int*)d_in[1];
    const void*  mask  = d_in[2];
    const float* v_emb = (const float*)d_in[3];
    const float* r_emb = (const float*)d_in[4];
    const float* tw    = (const float*)d_in[5];
    const float* tb    = (const float*)d_in[6];
    const float* Wq    = (const float*)d_in[7];
    const float* bq    = (const float*)d_in[8];
    const float* Wk    = (const float*)d_in[9];
    const float* bk    = (const float*)d_in[10];
    const float* Wv    = (const float*)d_in[11];
    const float* bv    = (const float*)d_in[12];
    const float* Wo    = (const float*)d_in[13];
    const float* bo    = (const float*)d_in[14];
    const float* Wc    = (const float*)d_in[15];
    const float* bc    = (const float*)d_in[16];
    float* out = (float*)d_out;

    int N  = in_sizes[0] / 4;
    int Mv = in_sizes[3] / 128;
    int Mr = in_sizes[4] / 128;

    tgn_detect_node<<<1, 256>>>(node, in_sizes[0]);
    tgn_detect_mask<<<1, 256>>>((const unsigned char*)mask, in_sizes[2]);

    tgn_prep<<<1, 128>>>(Wq, bq, Wo, bo, Wc, bc, tb);

    tgn_cosE<<<(int)(((long)DT_ROWS * 32 + 255) / 256), 256>>>(tw, tb);

    TSlice3 Pv;
    Pv.s[0] = { Wq,       nullptr, 256, 0, 128,   0, 1 };
    Pv.s[1] = { Wk,       nullptr, 384, 1, 256,   0, 0 };
    Pv.s[2] = { Wv,       nullptr, 384, 1, 256, 128, 0 };
    tgn_mma<<<dim3((Mv + 127) / 128, 3), 256>>>(v_emb, Mv, Pv);

    TSlice3 Pr;
    Pr.s[0] = { Wk + 128, nullptr, 384, 2, 256,   0, 0 };
    Pr.s[1] = { Wv + 128, nullptr, 384, 2, 256, 128, 0 };
    Pr.s[2] = Pr.s[0];
    tgn_mma<<<dim3((Mr + 127) / 128, 2), 256>>>(r_emb, Mr, Pr);

    TSlice3 Pt;
    Pt.s[0] = { Wk + 256, bk,      384, 3, 256,   0, 0 };
    Pt.s[1] = { Wv + 256, bv,      384, 3, 256, 128, 0 };
    Pt.s[2] = Pt.s[0];
    tgn_mma<<<dim3((DT_ROWS + 127) / 128, 2), 256>>>(nullptr, DT_ROWS, Pt);

    tgn_attn<<<N, 128>>>(node, nbr, mask, bc, out, N);
}